// round 1
// baseline (speedup 1.0000x reference)
#include <cuda_runtime.h>
#include <math.h>

#define S_LEN   4096
#define DMODEL  1024
#define NHEADS  16
#define HDIM    64

// Scratch (allocation-free rule: device globals)
__device__ float g_Q[S_LEN * DMODEL];
__device__ float g_K[S_LEN * DMODEL];
__device__ float g_V[S_LEN * DMODEL];
__device__ float g_A[S_LEN * DMODEL];

// ---------------------------------------------------------------------------
// GEMM: C[M,N] = A[M,K] @ W[K,N] + bias[N]
// BM=128, BN=128, BK=8, 256 threads, 8x8 per-thread tile.
// ---------------------------------------------------------------------------
#define BM 128
#define BN 128
#define BK 8
#define TM 8
#define TN 8

__global__ __launch_bounds__(256) void gemm_bias_kernel(
    const float* __restrict__ A, const float* __restrict__ W,
    const float* __restrict__ bias, float* __restrict__ C,
    int M, int N, int K)
{
    __shared__ float As[BK][BM];
    __shared__ float Bs[BK][BN];

    const int tid = threadIdx.x;
    const int bx = blockIdx.x;   // over N
    const int by = blockIdx.y;   // over M

    const int threadCol = tid % (BN / TN);   // 0..15
    const int threadRow = tid / (BN / TN);   // 0..15

    const int innerRowA = tid >> 1;          // 0..127
    const int innerColA = (tid & 1) * 4;     // 0 or 4
    const int innerRowB = tid >> 5;          // 0..7
    const int innerColB = (tid & 31) * 4;    // 0..124

    const float* Ag = A + (size_t)by * BM * K;
    const float* Wg = W + bx * BN;
    float*       Cg = C + (size_t)by * BM * N + bx * BN;

    float acc[TM][TN];
#pragma unroll
    for (int i = 0; i < TM; i++)
#pragma unroll
        for (int j = 0; j < TN; j++) acc[i][j] = 0.f;

    float regM[TM], regN[TN];

    for (int k0 = 0; k0 < K; k0 += BK) {
        float4 a = *(const float4*)(Ag + (size_t)innerRowA * K + k0 + innerColA);
        As[innerColA + 0][innerRowA] = a.x;
        As[innerColA + 1][innerRowA] = a.y;
        As[innerColA + 2][innerRowA] = a.z;
        As[innerColA + 3][innerRowA] = a.w;
        *(float4*)(&Bs[innerRowB][innerColB]) =
            *(const float4*)(Wg + (size_t)(k0 + innerRowB) * N + innerColB);
        __syncthreads();

#pragma unroll
        for (int k = 0; k < BK; k++) {
            *(float4*)(regM)     = *(float4*)(&As[k][threadRow * TM]);
            *(float4*)(regM + 4) = *(float4*)(&As[k][threadRow * TM + 4]);
            *(float4*)(regN)     = *(float4*)(&Bs[k][threadCol * TN]);
            *(float4*)(regN + 4) = *(float4*)(&Bs[k][threadCol * TN + 4]);
#pragma unroll
            for (int i = 0; i < TM; i++)
#pragma unroll
                for (int j = 0; j < TN; j++)
                    acc[i][j] += regM[i] * regN[j];
        }
        __syncthreads();
    }

#pragma unroll
    for (int i = 0; i < TM; i++) {
#pragma unroll
        for (int j = 0; j < TN; j += 4) {
            int col = threadCol * TN + j;
            float4 o;
            o.x = acc[i][j + 0] + bias[bx * BN + col + 0];
            o.y = acc[i][j + 1] + bias[bx * BN + col + 1];
            o.z = acc[i][j + 2] + bias[bx * BN + col + 2];
            o.w = acc[i][j + 3] + bias[bx * BN + col + 3];
            *(float4*)(&Cg[(size_t)(threadRow * TM + i) * N + col]) = o;
        }
    }
}

// ---------------------------------------------------------------------------
// Flash-attention: per (head, 64-query block). 64-key tiles, online softmax.
// Thread map (256 threads): qrow = tid/16 (owns 4 q rows), kcol = tid%16
// (owns 4 k cols for S, 4 d cols for O).
// ---------------------------------------------------------------------------
#define PAD 68   // row stride in floats (16B aligned, avoids worst conflicts)

__global__ __launch_bounds__(256) void attn_kernel(
    const float* __restrict__ Q, const float* __restrict__ K,
    const float* __restrict__ V, const int* __restrict__ mask,
    float* __restrict__ O)
{
    extern __shared__ float sm[];
    float* Qs = sm;                // 64*PAD
    float* Ks = Qs + 64 * PAD;     // 64*PAD
    float* Vs = Ks + 64 * PAD;     // 64*PAD
    float* Ps = Vs + 64 * PAD;     // 64*PAD
    float* ms = Ps + 64 * PAD;     // 64

    const int h   = blockIdx.x;    // head
    const int qb  = blockIdx.y;    // query block
    const int tid = threadIdx.x;
    const int qrow = tid >> 4;     // 0..15
    const int kcol = tid & 15;     // 0..15
    const int dbase = kcol * 4;

    // Load Q tile (64 x 64), coalesced float4
#pragma unroll
    for (int it = 0; it < 4; it++) {
        int lin = it * 256 + tid;      // float4 index 0..1023
        int row = lin >> 4, c4 = lin & 15;
        *(float4*)(Qs + row * PAD + c4 * 4) =
            *(const float4*)(Q + (size_t)(qb * 64 + row) * DMODEL + h * HDIM + c4 * 4);
    }

    float m_i[4], l_i[4], o[4][4];
#pragma unroll
    for (int i = 0; i < 4; i++) {
        m_i[i] = -1e30f; l_i[i] = 0.f;
#pragma unroll
        for (int j = 0; j < 4; j++) o[i][j] = 0.f;
    }

    for (int kb = 0; kb < S_LEN / 64; kb++) {
        // Load K, V tiles + mask
#pragma unroll
        for (int it = 0; it < 4; it++) {
            int lin = it * 256 + tid;
            int row = lin >> 4, c4 = lin & 15;
            size_t g = (size_t)(kb * 64 + row) * DMODEL + h * HDIM + c4 * 4;
            *(float4*)(Ks + row * PAD + c4 * 4) = *(const float4*)(K + g);
            *(float4*)(Vs + row * PAD + c4 * 4) = *(const float4*)(V + g);
        }
        if (tid < 64) ms[tid] = (mask[kb * 64 + tid] == 0) ? -1e9f : 0.f;
        __syncthreads();

        // S = Q @ K^T (4x4 per thread), float4 along d
        float s[4][4];
#pragma unroll
        for (int i = 0; i < 4; i++)
#pragma unroll
            for (int j = 0; j < 4; j++) s[i][j] = 0.f;

#pragma unroll
        for (int d = 0; d < HDIM; d += 4) {
            float4 qv[4], kv[4];
#pragma unroll
            for (int i = 0; i < 4; i++)
                qv[i] = *(float4*)(Qs + (qrow * 4 + i) * PAD + d);
#pragma unroll
            for (int j = 0; j < 4; j++)
                kv[j] = *(float4*)(Ks + (kcol * 4 + j) * PAD + d);
#pragma unroll
            for (int i = 0; i < 4; i++)
#pragma unroll
                for (int j = 0; j < 4; j++)
                    s[i][j] += qv[i].x * kv[j].x + qv[i].y * kv[j].y +
                               qv[i].z * kv[j].z + qv[i].w * kv[j].w;
        }

        // Online softmax per q row (16 threads per row, shfl reductions)
#pragma unroll
        for (int i = 0; i < 4; i++) {
            float mx = -1e30f;
#pragma unroll
            for (int j = 0; j < 4; j++) {
                s[i][j] = s[i][j] * 0.125f + ms[kcol * 4 + j];
                mx = fmaxf(mx, s[i][j]);
            }
#pragma unroll
            for (int off = 8; off >= 1; off >>= 1)
                mx = fmaxf(mx, __shfl_xor_sync(0xffffffffu, mx, off));
            float newm = fmaxf(m_i[i], mx);
            float sum = 0.f;
#pragma unroll
            for (int j = 0; j < 4; j++) {
                float p = __expf(s[i][j] - newm);
                s[i][j] = p;
                sum += p;
            }
#pragma unroll
            for (int off = 8; off >= 1; off >>= 1)
                sum += __shfl_xor_sync(0xffffffffu, sum, off);
            float fac = __expf(m_i[i] - newm);
            l_i[i] = l_i[i] * fac + sum;
            m_i[i] = newm;
#pragma unroll
            for (int j = 0; j < 4; j++) o[i][j] *= fac;
            // stage P to smem
#pragma unroll
            for (int j = 0; j < 4; j++)
                Ps[(qrow * 4 + i) * PAD + kcol * 4 + j] = s[i][j];
        }
        __syncthreads();

        // O += P @ V  (thread owns 4 q rows x 4 d cols)
#pragma unroll 8
        for (int k = 0; k < 64; k++) {
            float4 vv = *(float4*)(Vs + k * PAD + dbase);
#pragma unroll
            for (int i = 0; i < 4; i++) {
                float p = Ps[(qrow * 4 + i) * PAD + k];
                o[i][0] += p * vv.x;
                o[i][1] += p * vv.y;
                o[i][2] += p * vv.z;
                o[i][3] += p * vv.w;
            }
        }
        __syncthreads();   // before next tile overwrites Ks/Vs/Ps
    }

    // Normalize + write to g_A in [S, DMODEL] layout
#pragma unroll
    for (int i = 0; i < 4; i++) {
        float inv = 1.f / fmaxf(l_i[i], 1e-20f);
        float4 r;
        r.x = o[i][0] * inv; r.y = o[i][1] * inv;
        r.z = o[i][2] * inv; r.w = o[i][3] * inv;
        *(float4*)(O + (size_t)(qb * 64 + qrow * 4 + i) * DMODEL + h * HDIM + dbase) = r;
    }
}

// ---------------------------------------------------------------------------
extern "C" void kernel_launch(void* const* d_in, const int* in_sizes, int n_in,
                              void* d_out, int out_size)
{
    (void)in_sizes; (void)n_in; (void)out_size;
    const float* query = (const float*)d_in[0];
    const float* key   = (const float*)d_in[1];
    const float* value = (const float*)d_in[2];
    const int*   amask = (const int*)  d_in[3];
    const float* Wq = (const float*)d_in[4];
    const float* bq = (const float*)d_in[5];
    const float* Wk = (const float*)d_in[6];
    const float* bk = (const float*)d_in[7];
    const float* Wv = (const float*)d_in[8];
    const float* bv = (const float*)d_in[9];
    const float* Wo = (const float*)d_in[10];
    const float* bo = (const float*)d_in[11];
    float* out = (float*)d_out;

    float *Qp, *Kp, *Vp, *Ap;
    cudaGetSymbolAddress((void**)&Qp, g_Q);
    cudaGetSymbolAddress((void**)&Kp, g_K);
    cudaGetSymbolAddress((void**)&Vp, g_V);
    cudaGetSymbolAddress((void**)&Ap, g_A);

    dim3 gg(DMODEL / BN, S_LEN / BM);   // (8, 32)

    gemm_bias_kernel<<<gg, 256>>>(query, Wq, bq, Qp, S_LEN, DMODEL, DMODEL);
    gemm_bias_kernel<<<gg, 256>>>(key,   Wk, bk, Kp, S_LEN, DMODEL, DMODEL);
    gemm_bias_kernel<<<gg, 256>>>(value, Wv, bv, Vp, S_LEN, DMODEL, DMODEL);

    size_t smem = (size_t)(4 * 64 * PAD + 64) * sizeof(float);  // ~69.9 KB
    cudaFuncSetAttribute(attn_kernel,
                         cudaFuncAttributeMaxDynamicSharedMemorySize, (int)smem);
    attn_kernel<<<dim3(NHEADS, S_LEN / 64), 256, smem>>>(Qp, Kp, Vp, amask, Ap);

    gemm_bias_kernel<<<gg, 256>>>(Ap, Wo, bo, out, S_LEN, DMODEL, DMODEL);
}

// round 2
// speedup vs baseline: 3.7764x; 3.7764x over previous
#include <cuda_runtime.h>
#include <math.h>
#include <stdint.h>

#define S_LEN   4096
#define DMODEL  1024
#define NHEADS  16
#define HDIM    64

// Scratch (allocation-free rule: device globals)
__device__ float g_Q[S_LEN * DMODEL];
__device__ float g_K[S_LEN * DMODEL];
__device__ float g_V[S_LEN * DMODEL];
__device__ float g_A[S_LEN * DMODEL];

// ---------------------------------------------------------------------------
// Helpers: tf32 convert + mma.m16n8k8 tf32
// ---------------------------------------------------------------------------
__device__ __forceinline__ float to_tf32(float x) {
    float r;
    asm("cvt.rna.tf32.f32 %0, %1;" : "=f"(r) : "f"(x));
    return r;
}

__device__ __forceinline__ void mma8(float* c,
    uint32_t a0, uint32_t a1, uint32_t a2, uint32_t a3,
    uint32_t b0, uint32_t b1)
{
    asm volatile(
        "mma.sync.aligned.m16n8k8.row.col.f32.tf32.tf32.f32 "
        "{%0,%1,%2,%3}, {%4,%5,%6,%7}, {%8,%9}, {%0,%1,%2,%3};"
        : "+f"(c[0]), "+f"(c[1]), "+f"(c[2]), "+f"(c[3])
        : "r"(a0), "r"(a1), "r"(a2), "r"(a3), "r"(b0), "r"(b1));
}

__device__ __forceinline__ uint32_t f2u(float x) { return __float_as_uint(x); }

// ---------------------------------------------------------------------------
// TF32 GEMM: C[M,N] = A[M,K] @ W[K,N] + bias
// 256 threads, BM=128 BN=128 BK=16. 8 warps: 2x4, each 64m x 32n.
// As stride 20, Bs stride 136 (both conflict-free for frag patterns).
// ---------------------------------------------------------------------------
#define GBK 16
#define SA  20
#define SB  136

__global__ __launch_bounds__(256) void gemm_tf32(
    const float* __restrict__ A, const float* __restrict__ W,
    const float* __restrict__ bias, float* __restrict__ C,
    int M, int N, int K)
{
    __shared__ float As[128 * SA];
    __shared__ float Bs[GBK * SB];

    const int tid = threadIdx.x;
    const int lane = tid & 31;
    const int w = tid >> 5;
    const int wm = (w >> 2) * 64;   // 0 or 64
    const int wn = (w & 3) * 32;    // 0..96
    const int gid = lane >> 2;      // group id 0..7
    const int tig = lane & 3;       // thread in group 0..3

    const float* Ag = A + (size_t)blockIdx.y * 128 * K;
    const float* Wg = W + blockIdx.x * 128;

    // loader indices
    const int ar  = tid >> 2;        // 0..63
    const int ac4 = (tid & 3) * 4;   // 0,4,8,12
    const int br  = tid >> 5;        // 0..7
    const int bc4 = (tid & 31) * 4;  // 0..124

    float4 ra0, ra1, rb0, rb1;

    float acc[4][4][4];
#pragma unroll
    for (int mt = 0; mt < 4; mt++)
#pragma unroll
        for (int nt = 0; nt < 4; nt++)
#pragma unroll
            for (int e = 0; e < 4; e++) acc[mt][nt][e] = 0.f;

#define LOADG(k0) do { \
        ra0 = *(const float4*)(Ag + (size_t)ar * K + (k0) + ac4); \
        ra1 = *(const float4*)(Ag + (size_t)(ar + 64) * K + (k0) + ac4); \
        rb0 = *(const float4*)(Wg + (size_t)((k0) + br) * N + bc4); \
        rb1 = *(const float4*)(Wg + (size_t)((k0) + br + 8) * N + bc4); \
    } while (0)

#define STORES() do { \
        float4 t; \
        t.x = to_tf32(ra0.x); t.y = to_tf32(ra0.y); t.z = to_tf32(ra0.z); t.w = to_tf32(ra0.w); \
        *(float4*)(&As[ar * SA + ac4]) = t; \
        t.x = to_tf32(ra1.x); t.y = to_tf32(ra1.y); t.z = to_tf32(ra1.z); t.w = to_tf32(ra1.w); \
        *(float4*)(&As[(ar + 64) * SA + ac4]) = t; \
        t.x = to_tf32(rb0.x); t.y = to_tf32(rb0.y); t.z = to_tf32(rb0.z); t.w = to_tf32(rb0.w); \
        *(float4*)(&Bs[br * SB + bc4]) = t; \
        t.x = to_tf32(rb1.x); t.y = to_tf32(rb1.y); t.z = to_tf32(rb1.z); t.w = to_tf32(rb1.w); \
        *(float4*)(&Bs[(br + 8) * SB + bc4]) = t; \
    } while (0)

    const int NIT = K / GBK;
    LOADG(0);
    STORES();
    __syncthreads();

    for (int it = 0; it < NIT; it++) {
        if (it + 1 < NIT) LOADG((it + 1) * GBK);

#pragma unroll
        for (int ks = 0; ks < GBK; ks += 8) {
            uint32_t b[4][2];
#pragma unroll
            for (int nt = 0; nt < 4; nt++) {
                b[nt][0] = f2u(Bs[(ks + tig) * SB + wn + nt * 8 + gid]);
                b[nt][1] = f2u(Bs[(ks + tig + 4) * SB + wn + nt * 8 + gid]);
            }
#pragma unroll
            for (int mt = 0; mt < 4; mt++) {
                int r = wm + mt * 16 + gid;
                uint32_t a0 = f2u(As[r * SA + ks + tig]);
                uint32_t a1 = f2u(As[(r + 8) * SA + ks + tig]);
                uint32_t a2 = f2u(As[r * SA + ks + tig + 4]);
                uint32_t a3 = f2u(As[(r + 8) * SA + ks + tig + 4]);
#pragma unroll
                for (int nt = 0; nt < 4; nt++)
                    mma8(acc[mt][nt], a0, a1, a2, a3, b[nt][0], b[nt][1]);
            }
        }
        __syncthreads();
        if (it + 1 < NIT) {
            STORES();
            __syncthreads();
        }
    }

    // epilogue: add bias, store float2 pairs
#pragma unroll
    for (int nt = 0; nt < 4; nt++) {
        int col = blockIdx.x * 128 + wn + nt * 8 + 2 * tig;
        float b0 = bias[col], b1 = bias[col + 1];
#pragma unroll
        for (int mt = 0; mt < 4; mt++) {
            int row = blockIdx.y * 128 + wm + mt * 16 + gid;
            float2 o;
            o.x = acc[mt][nt][0] + b0; o.y = acc[mt][nt][1] + b1;
            *(float2*)(&C[(size_t)row * N + col]) = o;
            o.x = acc[mt][nt][2] + b0; o.y = acc[mt][nt][3] + b1;
            *(float2*)(&C[(size_t)(row + 8) * N + col]) = o;
        }
    }
#undef LOADG
#undef STORES
}

// ---------------------------------------------------------------------------
// TF32 flash attention. Block = (head, 64-query tile). 256 threads, 8 warps.
// Warp w: q-row strip = (w>>1)*16, key/d-column half = (w&1)*32 (4 n-tiles of 8).
// ---------------------------------------------------------------------------
#define SQ 68
#define SKS 68
#define SV 72
#define SP 68

__global__ __launch_bounds__(256) void attn_tf32(
    const float* __restrict__ Q, const float* __restrict__ K,
    const float* __restrict__ V, const int* __restrict__ mask,
    float* __restrict__ O)
{
    extern __shared__ float sm[];
    float* Qs   = sm;                  // 64*68 = 4352
    float* Ks   = Qs + 64 * SQ;        // 4352
    float* Vs   = Ks + 64 * SKS;       // 64*72 = 4608
    float* Ps   = Vs + 64 * SV;        // 4352
    float* ms   = Ps + 64 * SP;        // 64
    float* m_s  = ms + 64;             // 64
    float* l_s  = m_s + 64;            // 64
    float* fac_s= l_s + 64;            // 64
    float* wmax = fac_s + 64;          // 2*64
    float* wsum = wmax + 128;          // 2*64

    const int h   = blockIdx.x;
    const int qb  = blockIdx.y;
    const int tid = threadIdx.x;
    const int lane = tid & 31;
    const int w = tid >> 5;
    const int strip = (w >> 1) * 16;   // q-row strip base
    const int nh = (w & 1) * 32;       // column half base
    const int gid = lane >> 2;
    const int tig = lane & 3;

    // Load Q tile (64x64) with tf32 convert
#pragma unroll
    for (int it = 0; it < 4; it++) {
        int lin = it * 256 + tid;          // 0..1023 float4 slots
        int row = lin >> 4, c4 = (lin & 15) * 4;
        float4 v = *(const float4*)(Q + (size_t)(qb * 64 + row) * DMODEL + h * HDIM + c4);
        float4 t;
        t.x = to_tf32(v.x); t.y = to_tf32(v.y); t.z = to_tf32(v.z); t.w = to_tf32(v.w);
        *(float4*)(&Qs[row * SQ + c4]) = t;
    }
    if (tid < 64) { m_s[tid] = -1e30f; l_s[tid] = 0.f; }

    float o[4][4];
#pragma unroll
    for (int nt = 0; nt < 4; nt++)
#pragma unroll
        for (int e = 0; e < 4; e++) o[nt][e] = 0.f;

    const int r0 = strip + gid;  // first owned row (0..63), second is r0+8

    for (int kb = 0; kb < S_LEN / 64; kb++) {
        __syncthreads();  // previous iter done with Ks/Vs
        // Load K,V tiles (64x64 each) + mask
#pragma unroll
        for (int it = 0; it < 4; it++) {
            int lin = it * 256 + tid;
            int row = lin >> 4, c4 = (lin & 15) * 4;
            size_t g = (size_t)(kb * 64 + row) * DMODEL + h * HDIM + c4;
            float4 kv = *(const float4*)(K + g);
            float4 vv = *(const float4*)(V + g);
            float4 t;
            t.x = to_tf32(kv.x); t.y = to_tf32(kv.y); t.z = to_tf32(kv.z); t.w = to_tf32(kv.w);
            *(float4*)(&Ks[row * SKS + c4]) = t;
            t.x = to_tf32(vv.x); t.y = to_tf32(vv.y); t.z = to_tf32(vv.z); t.w = to_tf32(vv.w);
            *(float4*)(&Vs[row * SV + c4]) = t;
        }
        if (tid < 64) ms[tid] = (mask[kb * 64 + tid] == 0) ? -1e9f : 0.f;
        __syncthreads();

        // S = Q @ K^T : warp computes 16 rows x 32 cols (4 n-tiles)
        float s[4][4];
#pragma unroll
        for (int nt = 0; nt < 4; nt++)
#pragma unroll
            for (int e = 0; e < 4; e++) s[nt][e] = 0.f;

#pragma unroll
        for (int ks = 0; ks < HDIM; ks += 8) {
            uint32_t a0 = f2u(Qs[r0 * SQ + ks + tig]);
            uint32_t a1 = f2u(Qs[(r0 + 8) * SQ + ks + tig]);
            uint32_t a2 = f2u(Qs[r0 * SQ + ks + tig + 4]);
            uint32_t a3 = f2u(Qs[(r0 + 8) * SQ + ks + tig + 4]);
#pragma unroll
            for (int nt = 0; nt < 4; nt++) {
                int kr = nh + nt * 8 + gid;  // key index
                uint32_t b0 = f2u(Ks[kr * SKS + ks + tig]);
                uint32_t b1 = f2u(Ks[kr * SKS + ks + tig + 4]);
                mma8(s[nt], a0, a1, a2, a3, b0, b1);
            }
        }

        // scale + mask + per-warp row max
        float mx0 = -1e30f, mx1 = -1e30f;
#pragma unroll
        for (int nt = 0; nt < 4; nt++) {
            int col = nh + nt * 8 + 2 * tig;
            float mk0 = ms[col], mk1 = ms[col + 1];
            s[nt][0] = s[nt][0] * 0.125f + mk0;
            s[nt][1] = s[nt][1] * 0.125f + mk1;
            s[nt][2] = s[nt][2] * 0.125f + mk0;
            s[nt][3] = s[nt][3] * 0.125f + mk1;
            mx0 = fmaxf(mx0, fmaxf(s[nt][0], s[nt][1]));
            mx1 = fmaxf(mx1, fmaxf(s[nt][2], s[nt][3]));
        }
        mx0 = fmaxf(mx0, __shfl_xor_sync(0xffffffffu, mx0, 1));
        mx0 = fmaxf(mx0, __shfl_xor_sync(0xffffffffu, mx0, 2));
        mx1 = fmaxf(mx1, __shfl_xor_sync(0xffffffffu, mx1, 1));
        mx1 = fmaxf(mx1, __shfl_xor_sync(0xffffffffu, mx1, 2));
        if (tig == 0) {
            wmax[(w & 1) * 64 + r0]     = mx0;
            wmax[(w & 1) * 64 + r0 + 8] = mx1;
        }
        __syncthreads();

        if (tid < 64) {
            float mx = fmaxf(wmax[tid], wmax[64 + tid]);
            float mp = m_s[tid];
            float nm = fmaxf(mp, mx);
            fac_s[tid] = __expf(mp - nm);
            m_s[tid] = nm;
        }
        __syncthreads();

        // p = exp(s - m), partial row sums, stage P to smem, rescale O
        float nm0 = m_s[r0], nm1 = m_s[r0 + 8];
        float f0 = fac_s[r0], f1 = fac_s[r0 + 8];
        float sum0 = 0.f, sum1 = 0.f;
#pragma unroll
        for (int nt = 0; nt < 4; nt++) {
            float p0 = __expf(s[nt][0] - nm0);
            float p1 = __expf(s[nt][1] - nm0);
            float p2 = __expf(s[nt][2] - nm1);
            float p3 = __expf(s[nt][3] - nm1);
            sum0 += p0 + p1; sum1 += p2 + p3;
            int col = nh + nt * 8 + 2 * tig;
            float2 st;
            st.x = to_tf32(p0); st.y = to_tf32(p1);
            *(float2*)(&Ps[r0 * SP + col]) = st;
            st.x = to_tf32(p2); st.y = to_tf32(p3);
            *(float2*)(&Ps[(r0 + 8) * SP + col]) = st;
            o[nt][0] *= f0; o[nt][1] *= f0;
            o[nt][2] *= f1; o[nt][3] *= f1;
        }
        sum0 += __shfl_xor_sync(0xffffffffu, sum0, 1);
        sum0 += __shfl_xor_sync(0xffffffffu, sum0, 2);
        sum1 += __shfl_xor_sync(0xffffffffu, sum1, 1);
        sum1 += __shfl_xor_sync(0xffffffffu, sum1, 2);
        if (tig == 0) {
            wsum[(w & 1) * 64 + r0]     = sum0;
            wsum[(w & 1) * 64 + r0 + 8] = sum1;
        }
        __syncthreads();

        if (tid < 64)
            l_s[tid] = l_s[tid] * fac_s[tid] + wsum[tid] + wsum[64 + tid];

        // O += P @ V : k over 64 keys
#pragma unroll
        for (int ks = 0; ks < 64; ks += 8) {
            uint32_t a0 = f2u(Ps[r0 * SP + ks + tig]);
            uint32_t a1 = f2u(Ps[(r0 + 8) * SP + ks + tig]);
            uint32_t a2 = f2u(Ps[r0 * SP + ks + tig + 4]);
            uint32_t a3 = f2u(Ps[(r0 + 8) * SP + ks + tig + 4]);
#pragma unroll
            for (int nt = 0; nt < 4; nt++) {
                int dc = nh + nt * 8 + gid;  // d column
                uint32_t b0 = f2u(Vs[(ks + tig) * SV + dc]);
                uint32_t b1 = f2u(Vs[(ks + tig + 4) * SV + dc]);
                mma8(o[nt], a0, a1, a2, a3, b0, b1);
            }
        }
    }
    __syncthreads();

    // normalize + write
    float inv0 = 1.f / fmaxf(l_s[r0], 1e-20f);
    float inv1 = 1.f / fmaxf(l_s[r0 + 8], 1e-20f);
#pragma unroll
    for (int nt = 0; nt < 4; nt++) {
        int col = h * HDIM + nh + nt * 8 + 2 * tig;
        float2 r;
        r.x = o[nt][0] * inv0; r.y = o[nt][1] * inv0;
        *(float2*)(&O[(size_t)(qb * 64 + r0) * DMODEL + col]) = r;
        r.x = o[nt][2] * inv1; r.y = o[nt][3] * inv1;
        *(float2*)(&O[(size_t)(qb * 64 + r0 + 8) * DMODEL + col]) = r;
    }
}

// ---------------------------------------------------------------------------
extern "C" void kernel_launch(void* const* d_in, const int* in_sizes, int n_in,
                              void* d_out, int out_size)
{
    (void)in_sizes; (void)n_in; (void)out_size;
    const float* query = (const float*)d_in[0];
    const float* key   = (const float*)d_in[1];
    const float* value = (const float*)d_in[2];
    const int*   amask = (const int*)  d_in[3];
    const float* Wq = (const float*)d_in[4];
    const float* bq = (const float*)d_in[5];
    const float* Wk = (const float*)d_in[6];
    const float* bk = (const float*)d_in[7];
    const float* Wv = (const float*)d_in[8];
    const float* bv = (const float*)d_in[9];
    const float* Wo = (const float*)d_in[10];
    const float* bo = (const float*)d_in[11];
    float* out = (float*)d_out;

    float *Qp, *Kp, *Vp, *Ap;
    cudaGetSymbolAddress((void**)&Qp, g_Q);
    cudaGetSymbolAddress((void**)&Kp, g_K);
    cudaGetSymbolAddress((void**)&Vp, g_V);
    cudaGetSymbolAddress((void**)&Ap, g_A);

    dim3 gg(DMODEL / 128, S_LEN / 128);   // (8, 32)

    gemm_tf32<<<gg, 256>>>(query, Wq, bq, Qp, S_LEN, DMODEL, DMODEL);
    gemm_tf32<<<gg, 256>>>(key,   Wk, bk, Kp, S_LEN, DMODEL, DMODEL);
    gemm_tf32<<<gg, 256>>>(value, Wv, bv, Vp, S_LEN, DMODEL, DMODEL);

    size_t smem = (size_t)(64 * SQ + 64 * SKS + 64 * SV + 64 * SP + 64 * 4 + 256)
                  * sizeof(float);
    static bool attr_set = false;
    if (!attr_set) {
        cudaFuncSetAttribute(attn_tf32,
                             cudaFuncAttributeMaxDynamicSharedMemorySize, (int)smem);
        attr_set = true;
    }
    attn_tf32<<<dim3(NHEADS, S_LEN / 64), 256, smem>>>(Qp, Kp, Vp, amask, Ap);

    gemm_tf32<<<gg, 256>>>(Ap, Wo, bo, out, S_LEN, DMODEL, DMODEL);
}

// round 3
// speedup vs baseline: 4.5175x; 1.1962x over previous
#include <cuda_runtime.h>
#include <math.h>
#include <stdint.h>

#define S_LEN   4096
#define DMODEL  1024
#define NHEADS  16
#define HDIM    64

// Scratch (allocation-free rule: device globals)
__device__ float g_Q[S_LEN * DMODEL];
__device__ float g_K[S_LEN * DMODEL];
__device__ float g_V[S_LEN * DMODEL];
__device__ float g_A[S_LEN * DMODEL];

// ---------------------------------------------------------------------------
// Helpers: tf32 convert + mma.m16n8k8 tf32
// ---------------------------------------------------------------------------
__device__ __forceinline__ float to_tf32(float x) {
    float r;
    asm("cvt.rna.tf32.f32 %0, %1;" : "=f"(r) : "f"(x));
    return r;
}

__device__ __forceinline__ void mma8(float* c,
    uint32_t a0, uint32_t a1, uint32_t a2, uint32_t a3,
    uint32_t b0, uint32_t b1)
{
    asm volatile(
        "mma.sync.aligned.m16n8k8.row.col.f32.tf32.tf32.f32 "
        "{%0,%1,%2,%3}, {%4,%5,%6,%7}, {%8,%9}, {%0,%1,%2,%3};"
        : "+f"(c[0]), "+f"(c[1]), "+f"(c[2]), "+f"(c[3])
        : "r"(a0), "r"(a1), "r"(a2), "r"(a3), "r"(b0), "r"(b1));
}

__device__ __forceinline__ uint32_t f2u(float x) { return __float_as_uint(x); }

// ---------------------------------------------------------------------------
// TF32 GEMM: C[M,N] = A[M,K] @ W[K,N] + bias  (unchanged from R1 — known good)
// ---------------------------------------------------------------------------
#define GBK 16
#define SA  20
#define SB  136

__global__ __launch_bounds__(256) void gemm_tf32(
    const float* __restrict__ A, const float* __restrict__ W,
    const float* __restrict__ bias, float* __restrict__ C,
    int M, int N, int K)
{
    __shared__ float As[128 * SA];
    __shared__ float Bs[GBK * SB];

    const int tid = threadIdx.x;
    const int lane = tid & 31;
    const int w = tid >> 5;
    const int wm = (w >> 2) * 64;
    const int wn = (w & 3) * 32;
    const int gid = lane >> 2;
    const int tig = lane & 3;

    const float* Ag = A + (size_t)blockIdx.y * 128 * K;
    const float* Wg = W + blockIdx.x * 128;

    const int ar  = tid >> 2;
    const int ac4 = (tid & 3) * 4;
    const int br  = tid >> 5;
    const int bc4 = (tid & 31) * 4;

    float4 ra0, ra1, rb0, rb1;

    float acc[4][4][4];
#pragma unroll
    for (int mt = 0; mt < 4; mt++)
#pragma unroll
        for (int nt = 0; nt < 4; nt++)
#pragma unroll
            for (int e = 0; e < 4; e++) acc[mt][nt][e] = 0.f;

#define LOADG(k0) do { \
        ra0 = *(const float4*)(Ag + (size_t)ar * K + (k0) + ac4); \
        ra1 = *(const float4*)(Ag + (size_t)(ar + 64) * K + (k0) + ac4); \
        rb0 = *(const float4*)(Wg + (size_t)((k0) + br) * N + bc4); \
        rb1 = *(const float4*)(Wg + (size_t)((k0) + br + 8) * N + bc4); \
    } while (0)

#define STORES() do { \
        float4 t; \
        t.x = to_tf32(ra0.x); t.y = to_tf32(ra0.y); t.z = to_tf32(ra0.z); t.w = to_tf32(ra0.w); \
        *(float4*)(&As[ar * SA + ac4]) = t; \
        t.x = to_tf32(ra1.x); t.y = to_tf32(ra1.y); t.z = to_tf32(ra1.z); t.w = to_tf32(ra1.w); \
        *(float4*)(&As[(ar + 64) * SA + ac4]) = t; \
        t.x = to_tf32(rb0.x); t.y = to_tf32(rb0.y); t.z = to_tf32(rb0.z); t.w = to_tf32(rb0.w); \
        *(float4*)(&Bs[br * SB + bc4]) = t; \
        t.x = to_tf32(rb1.x); t.y = to_tf32(rb1.y); t.z = to_tf32(rb1.z); t.w = to_tf32(rb1.w); \
        *(float4*)(&Bs[(br + 8) * SB + bc4]) = t; \
    } while (0)

    const int NIT = K / GBK;
    LOADG(0);
    STORES();
    __syncthreads();

    for (int it = 0; it < NIT; it++) {
        if (it + 1 < NIT) LOADG((it + 1) * GBK);

#pragma unroll
        for (int ks = 0; ks < GBK; ks += 8) {
            uint32_t b[4][2];
#pragma unroll
            for (int nt = 0; nt < 4; nt++) {
                b[nt][0] = f2u(Bs[(ks + tig) * SB + wn + nt * 8 + gid]);
                b[nt][1] = f2u(Bs[(ks + tig + 4) * SB + wn + nt * 8 + gid]);
            }
#pragma unroll
            for (int mt = 0; mt < 4; mt++) {
                int r = wm + mt * 16 + gid;
                uint32_t a0 = f2u(As[r * SA + ks + tig]);
                uint32_t a1 = f2u(As[(r + 8) * SA + ks + tig]);
                uint32_t a2 = f2u(As[r * SA + ks + tig + 4]);
                uint32_t a3 = f2u(As[(r + 8) * SA + ks + tig + 4]);
#pragma unroll
                for (int nt = 0; nt < 4; nt++)
                    mma8(acc[mt][nt], a0, a1, a2, a3, b[nt][0], b[nt][1]);
            }
        }
        __syncthreads();
        if (it + 1 < NIT) {
            STORES();
            __syncthreads();
        }
    }

#pragma unroll
    for (int nt = 0; nt < 4; nt++) {
        int col = blockIdx.x * 128 + wn + nt * 8 + 2 * tig;
        float b0 = bias[col], b1 = bias[col + 1];
#pragma unroll
        for (int mt = 0; mt < 4; mt++) {
            int row = blockIdx.y * 128 + wm + mt * 16 + gid;
            float2 o;
            o.x = acc[mt][nt][0] + b0; o.y = acc[mt][nt][1] + b1;
            *(float2*)(&C[(size_t)row * N + col]) = o;
            o.x = acc[mt][nt][2] + b0; o.y = acc[mt][nt][3] + b1;
            *(float2*)(&C[(size_t)(row + 8) * N + col]) = o;
        }
    }
#undef LOADG
#undef STORES
}

// ---------------------------------------------------------------------------
// TF32 flash attention v2: 128 threads, 4 warps. Each warp owns 32 q-rows x
// ALL 64 key cols -> fully warp-local online softmax (no cross-warp smem
// exchange, 2 syncthreads per key tile). CTA covers 128 q-rows.
// ---------------------------------------------------------------------------
#define SQ  68
#define SKS 68
#define SV  72
#define SP  68

__global__ __launch_bounds__(128) void attn_tf32(
    const float* __restrict__ Q, const float* __restrict__ K,
    const float* __restrict__ V, const int* __restrict__ mask,
    float* __restrict__ O)
{
    extern __shared__ float sm[];
    float* Qs = sm;                 // 128*68
    float* Ks = Qs + 128 * SQ;      // 64*68
    float* Vs = Ks + 64 * SKS;      // 64*72
    float* Ps = Vs + 64 * SV;       // 128*68
    float* ms = Ps + 128 * SP;      // 64

    const int h   = blockIdx.x;
    const int qb  = blockIdx.y;
    const int tid = threadIdx.x;
    const int lane = tid & 31;
    const int w = tid >> 5;
    const int wbase = w * 32;
    const int gid = lane >> 2;
    const int tig = lane & 3;

    const float LOG2E = 1.4426950408889634f;
    const float SCALE = 0.125f * LOG2E;

    // Load Q tile (128 x 64), cvt to tf32
#pragma unroll
    for (int it = 0; it < 16; it++) {
        int lin = it * 128 + tid;           // 0..2047 float4 slots
        int row = lin >> 4, c4 = (lin & 15) * 4;
        float4 v = *(const float4*)(Q + (size_t)(qb * 128 + row) * DMODEL + h * HDIM + c4);
        float4 t;
        t.x = to_tf32(v.x); t.y = to_tf32(v.y); t.z = to_tf32(v.z); t.w = to_tf32(v.w);
        *(float4*)(&Qs[row * SQ + c4]) = t;
    }

    float o[2][8][4];
    float m_st[2][2], l_st[2][2];
#pragma unroll
    for (int mt = 0; mt < 2; mt++) {
        m_st[mt][0] = -1e30f; m_st[mt][1] = -1e30f;
        l_st[mt][0] = 0.f;    l_st[mt][1] = 0.f;
#pragma unroll
        for (int nt = 0; nt < 8; nt++)
#pragma unroll
            for (int e = 0; e < 4; e++) o[mt][nt][e] = 0.f;
    }

    for (int kb = 0; kb < S_LEN / 64; kb++) {
        __syncthreads();   // all warps done with Ks/Vs from previous iter
        // Load K,V tiles (64x64 each)
#pragma unroll
        for (int it = 0; it < 8; it++) {
            int lin = it * 128 + tid;       // 0..1023 float4 slots
            int row = lin >> 4, c4 = (lin & 15) * 4;
            size_t g = (size_t)(kb * 64 + row) * DMODEL + h * HDIM + c4;
            float4 kv = *(const float4*)(K + g);
            float4 vv = *(const float4*)(V + g);
            float4 t;
            t.x = to_tf32(kv.x); t.y = to_tf32(kv.y); t.z = to_tf32(kv.z); t.w = to_tf32(kv.w);
            *(float4*)(&Ks[row * SKS + c4]) = t;
            t.x = to_tf32(vv.x); t.y = to_tf32(vv.y); t.z = to_tf32(vv.z); t.w = to_tf32(vv.w);
            *(float4*)(&Vs[row * SV + c4]) = t;
        }
        if (tid < 64) ms[tid] = (mask[kb * 64 + tid] == 0) ? -1.0e9f * LOG2E : 0.f;
        __syncthreads();

        // ---- S = Q @ K^T : warp computes 32 rows x 64 cols ----
        float s[2][8][4];
#pragma unroll
        for (int mt = 0; mt < 2; mt++)
#pragma unroll
            for (int nt = 0; nt < 8; nt++)
#pragma unroll
                for (int e = 0; e < 4; e++) s[mt][nt][e] = 0.f;

#pragma unroll
        for (int ks = 0; ks < HDIM; ks += 8) {
            uint32_t a[2][4];
#pragma unroll
            for (int mt = 0; mt < 2; mt++) {
                int r = wbase + mt * 16 + gid;
                a[mt][0] = f2u(Qs[r * SQ + ks + tig]);
                a[mt][1] = f2u(Qs[(r + 8) * SQ + ks + tig]);
                a[mt][2] = f2u(Qs[r * SQ + ks + tig + 4]);
                a[mt][3] = f2u(Qs[(r + 8) * SQ + ks + tig + 4]);
            }
#pragma unroll
            for (int nt = 0; nt < 8; nt++) {
                int kr = nt * 8 + gid;
                uint32_t b0 = f2u(Ks[kr * SKS + ks + tig]);
                uint32_t b1 = f2u(Ks[kr * SKS + ks + tig + 4]);
                mma8(s[0][nt], a[0][0], a[0][1], a[0][2], a[0][3], b0, b1);
                mma8(s[1][nt], a[1][0], a[1][1], a[1][2], a[1][3], b0, b1);
            }
        }

        // ---- warp-local online softmax (log2 domain) ----
#pragma unroll
        for (int mt = 0; mt < 2; mt++) {
            int r0 = wbase + mt * 16 + gid;
            float mx0 = -1e30f, mx1 = -1e30f;
#pragma unroll
            for (int nt = 0; nt < 8; nt++) {
                int col = nt * 8 + 2 * tig;
                float mk0 = ms[col], mk1 = ms[col + 1];
                s[mt][nt][0] = s[mt][nt][0] * SCALE + mk0;
                s[mt][nt][1] = s[mt][nt][1] * SCALE + mk1;
                s[mt][nt][2] = s[mt][nt][2] * SCALE + mk0;
                s[mt][nt][3] = s[mt][nt][3] * SCALE + mk1;
                mx0 = fmaxf(mx0, fmaxf(s[mt][nt][0], s[mt][nt][1]));
                mx1 = fmaxf(mx1, fmaxf(s[mt][nt][2], s[mt][nt][3]));
            }
            mx0 = fmaxf(mx0, __shfl_xor_sync(0xffffffffu, mx0, 1));
            mx0 = fmaxf(mx0, __shfl_xor_sync(0xffffffffu, mx0, 2));
            mx1 = fmaxf(mx1, __shfl_xor_sync(0xffffffffu, mx1, 1));
            mx1 = fmaxf(mx1, __shfl_xor_sync(0xffffffffu, mx1, 2));

            float nm0 = fmaxf(m_st[mt][0], mx0);
            float nm1 = fmaxf(m_st[mt][1], mx1);
            float f0 = exp2f(m_st[mt][0] - nm0);
            float f1 = exp2f(m_st[mt][1] - nm1);
            m_st[mt][0] = nm0; m_st[mt][1] = nm1;

            float sum0 = 0.f, sum1 = 0.f;
#pragma unroll
            for (int nt = 0; nt < 8; nt++) {
                float p0 = exp2f(s[mt][nt][0] - nm0);
                float p1 = exp2f(s[mt][nt][1] - nm0);
                float p2 = exp2f(s[mt][nt][2] - nm1);
                float p3 = exp2f(s[mt][nt][3] - nm1);
                sum0 += p0 + p1; sum1 += p2 + p3;
                int col = nt * 8 + 2 * tig;
                float2 st;
                st.x = to_tf32(p0); st.y = to_tf32(p1);
                *(float2*)(&Ps[r0 * SP + col]) = st;
                st.x = to_tf32(p2); st.y = to_tf32(p3);
                *(float2*)(&Ps[(r0 + 8) * SP + col]) = st;
                o[mt][nt][0] *= f0; o[mt][nt][1] *= f0;
                o[mt][nt][2] *= f1; o[mt][nt][3] *= f1;
            }
            sum0 += __shfl_xor_sync(0xffffffffu, sum0, 1);
            sum0 += __shfl_xor_sync(0xffffffffu, sum0, 2);
            sum1 += __shfl_xor_sync(0xffffffffu, sum1, 1);
            sum1 += __shfl_xor_sync(0xffffffffu, sum1, 2);
            l_st[mt][0] = l_st[mt][0] * f0 + sum0;
            l_st[mt][1] = l_st[mt][1] * f1 + sum1;
        }
        __syncwarp();   // Ps rows are warp-private; order stores before loads

        // ---- O += P @ V ----
#pragma unroll
        for (int ks = 0; ks < 64; ks += 8) {
            uint32_t a[2][4];
#pragma unroll
            for (int mt = 0; mt < 2; mt++) {
                int r = wbase + mt * 16 + gid;
                a[mt][0] = f2u(Ps[r * SP + ks + tig]);
                a[mt][1] = f2u(Ps[(r + 8) * SP + ks + tig]);
                a[mt][2] = f2u(Ps[r * SP + ks + tig + 4]);
                a[mt][3] = f2u(Ps[(r + 8) * SP + ks + tig + 4]);
            }
#pragma unroll
            for (int nt = 0; nt < 8; nt++) {
                int dc = nt * 8 + gid;
                uint32_t b0 = f2u(Vs[(ks + tig) * SV + dc]);
                uint32_t b1 = f2u(Vs[(ks + tig + 4) * SV + dc]);
                mma8(o[0][nt], a[0][0], a[0][1], a[0][2], a[0][3], b0, b1);
                mma8(o[1][nt], a[1][0], a[1][1], a[1][2], a[1][3], b0, b1);
            }
        }
    }

    // normalize + write
#pragma unroll
    for (int mt = 0; mt < 2; mt++) {
        int r0 = wbase + mt * 16 + gid;
        float inv0 = 1.f / fmaxf(l_st[mt][0], 1e-20f);
        float inv1 = 1.f / fmaxf(l_st[mt][1], 1e-20f);
#pragma unroll
        for (int nt = 0; nt < 8; nt++) {
            int col = h * HDIM + nt * 8 + 2 * tig;
            float2 r;
            r.x = o[mt][nt][0] * inv0; r.y = o[mt][nt][1] * inv0;
            *(float2*)(&O[(size_t)(qb * 128 + r0) * DMODEL + col]) = r;
            r.x = o[mt][nt][2] * inv1; r.y = o[mt][nt][3] * inv1;
            *(float2*)(&O[(size_t)(qb * 128 + r0 + 8) * DMODEL + col]) = r;
        }
    }
}

// ---------------------------------------------------------------------------
extern "C" void kernel_launch(void* const* d_in, const int* in_sizes, int n_in,
                              void* d_out, int out_size)
{
    (void)in_sizes; (void)n_in; (void)out_size;
    const float* query = (const float*)d_in[0];
    const float* key   = (const float*)d_in[1];
    const float* value = (const float*)d_in[2];
    const int*   amask = (const int*)  d_in[3];
    const float* Wq = (const float*)d_in[4];
    const float* bq = (const float*)d_in[5];
    const float* Wk = (const float*)d_in[6];
    const float* bk = (const float*)d_in[7];
    const float* Wv = (const float*)d_in[8];
    const float* bv = (const float*)d_in[9];
    const float* Wo = (const float*)d_in[10];
    const float* bo = (const float*)d_in[11];
    float* out = (float*)d_out;

    float *Qp, *Kp, *Vp, *Ap;
    cudaGetSymbolAddress((void**)&Qp, g_Q);
    cudaGetSymbolAddress((void**)&Kp, g_K);
    cudaGetSymbolAddress((void**)&Vp, g_V);
    cudaGetSymbolAddress((void**)&Ap, g_A);

    dim3 gg(DMODEL / 128, S_LEN / 128);   // (8, 32)

    gemm_tf32<<<gg, 256>>>(query, Wq, bq, Qp, S_LEN, DMODEL, DMODEL);
    gemm_tf32<<<gg, 256>>>(key,   Wk, bk, Kp, S_LEN, DMODEL, DMODEL);
    gemm_tf32<<<gg, 256>>>(value, Wv, bv, Vp, S_LEN, DMODEL, DMODEL);

    size_t smem = (size_t)(128 * SQ + 64 * SKS + 64 * SV + 128 * SP + 64)
                  * sizeof(float);   // ~105.7 KB
    cudaFuncSetAttribute(attn_tf32,
                         cudaFuncAttributeMaxDynamicSharedMemorySize, (int)smem);
    attn_tf32<<<dim3(NHEADS, S_LEN / 128), 128, smem>>>(Qp, Kp, Vp, amask, Ap);

    gemm_tf32<<<gg, 256>>>(Ap, Wo, bo, out, S_LEN, DMODEL, DMODEL);
}

// round 4
// speedup vs baseline: 4.5268x; 1.0021x over previous
#include <cuda_runtime.h>
#include <math.h>
#include <stdint.h>

#define S_LEN   4096
#define DMODEL  1024
#define NHEADS  16
#define HDIM    64

// Scratch (allocation-free rule: device globals)
__device__ float g_Q[S_LEN * DMODEL];
__device__ float g_K[S_LEN * DMODEL];
__device__ float g_V[S_LEN * DMODEL];
__device__ float g_A[S_LEN * DMODEL];

// ---------------------------------------------------------------------------
// Helpers: tf32 convert + mma.m16n8k8 tf32
// ---------------------------------------------------------------------------
__device__ __forceinline__ float to_tf32(float x) {
    float r;
    asm("cvt.rna.tf32.f32 %0, %1;" : "=f"(r) : "f"(x));
    return r;
}

__device__ __forceinline__ void mma8(float* c,
    uint32_t a0, uint32_t a1, uint32_t a2, uint32_t a3,
    uint32_t b0, uint32_t b1)
{
    asm volatile(
        "mma.sync.aligned.m16n8k8.row.col.f32.tf32.tf32.f32 "
        "{%0,%1,%2,%3}, {%4,%5,%6,%7}, {%8,%9}, {%0,%1,%2,%3};"
        : "+f"(c[0]), "+f"(c[1]), "+f"(c[2]), "+f"(c[3])
        : "r"(a0), "r"(a1), "r"(a2), "r"(a3), "r"(b0), "r"(b1));
}

__device__ __forceinline__ uint32_t f2u(float x) { return __float_as_uint(x); }

// ---------------------------------------------------------------------------
// TF32 GEMM body (BM=128 BN=128 BK=16, 256 thr, 8 warps 2x4, 64x32 each)
// ---------------------------------------------------------------------------
#define GBK 16
#define SA  20
#define SB  136

__device__ __forceinline__ void gemm_body(
    const float* __restrict__ A, const float* __restrict__ W,
    const float* __restrict__ bias, float* __restrict__ C,
    int N, int K, int bx, int by)
{
    __shared__ float As[128 * SA];
    __shared__ float Bs[GBK * SB];

    const int tid = threadIdx.x;
    const int lane = tid & 31;
    const int w = tid >> 5;
    const int wm = (w >> 2) * 64;
    const int wn = (w & 3) * 32;
    const int gid = lane >> 2;
    const int tig = lane & 3;

    const float* Ag = A + (size_t)by * 128 * K;
    const float* Wg = W + bx * 128;

    const int ar  = tid >> 2;
    const int ac4 = (tid & 3) * 4;
    const int br  = tid >> 5;
    const int bc4 = (tid & 31) * 4;

    float4 ra0, ra1, rb0, rb1;

    float acc[4][4][4];
#pragma unroll
    for (int mt = 0; mt < 4; mt++)
#pragma unroll
        for (int nt = 0; nt < 4; nt++)
#pragma unroll
            for (int e = 0; e < 4; e++) acc[mt][nt][e] = 0.f;

#define LOADG(k0) do { \
        ra0 = *(const float4*)(Ag + (size_t)ar * K + (k0) + ac4); \
        ra1 = *(const float4*)(Ag + (size_t)(ar + 64) * K + (k0) + ac4); \
        rb0 = *(const float4*)(Wg + (size_t)((k0) + br) * N + bc4); \
        rb1 = *(const float4*)(Wg + (size_t)((k0) + br + 8) * N + bc4); \
    } while (0)

#define STORES() do { \
        float4 t; \
        t.x = to_tf32(ra0.x); t.y = to_tf32(ra0.y); t.z = to_tf32(ra0.z); t.w = to_tf32(ra0.w); \
        *(float4*)(&As[ar * SA + ac4]) = t; \
        t.x = to_tf32(ra1.x); t.y = to_tf32(ra1.y); t.z = to_tf32(ra1.z); t.w = to_tf32(ra1.w); \
        *(float4*)(&As[(ar + 64) * SA + ac4]) = t; \
        t.x = to_tf32(rb0.x); t.y = to_tf32(rb0.y); t.z = to_tf32(rb0.z); t.w = to_tf32(rb0.w); \
        *(float4*)(&Bs[br * SB + bc4]) = t; \
        t.x = to_tf32(rb1.x); t.y = to_tf32(rb1.y); t.z = to_tf32(rb1.z); t.w = to_tf32(rb1.w); \
        *(float4*)(&Bs[(br + 8) * SB + bc4]) = t; \
    } while (0)

    const int NIT = K / GBK;
    LOADG(0);
    STORES();
    __syncthreads();

    for (int it = 0; it < NIT; it++) {
        if (it + 1 < NIT) LOADG((it + 1) * GBK);

#pragma unroll
        for (int ks = 0; ks < GBK; ks += 8) {
            uint32_t b[4][2];
#pragma unroll
            for (int nt = 0; nt < 4; nt++) {
                b[nt][0] = f2u(Bs[(ks + tig) * SB + wn + nt * 8 + gid]);
                b[nt][1] = f2u(Bs[(ks + tig + 4) * SB + wn + nt * 8 + gid]);
            }
#pragma unroll
            for (int mt = 0; mt < 4; mt++) {
                int r = wm + mt * 16 + gid;
                uint32_t a0 = f2u(As[r * SA + ks + tig]);
                uint32_t a1 = f2u(As[(r + 8) * SA + ks + tig]);
                uint32_t a2 = f2u(As[r * SA + ks + tig + 4]);
                uint32_t a3 = f2u(As[(r + 8) * SA + ks + tig + 4]);
#pragma unroll
                for (int nt = 0; nt < 4; nt++)
                    mma8(acc[mt][nt], a0, a1, a2, a3, b[nt][0], b[nt][1]);
            }
        }
        __syncthreads();
        if (it + 1 < NIT) {
            STORES();
            __syncthreads();
        }
    }

#pragma unroll
    for (int nt = 0; nt < 4; nt++) {
        int col = bx * 128 + wn + nt * 8 + 2 * tig;
        float b0 = bias[col], b1 = bias[col + 1];
#pragma unroll
        for (int mt = 0; mt < 4; mt++) {
            int row = by * 128 + wm + mt * 16 + gid;
            float2 o;
            o.x = acc[mt][nt][0] + b0; o.y = acc[mt][nt][1] + b1;
            *(float2*)(&C[(size_t)row * N + col]) = o;
            o.x = acc[mt][nt][2] + b0; o.y = acc[mt][nt][3] + b1;
            *(float2*)(&C[(size_t)(row + 8) * N + col]) = o;
        }
    }
#undef LOADG
#undef STORES
}

// Fused Q/K/V projection: blockIdx.z selects which projection.
__global__ __launch_bounds__(256) void gemm_qkv(
    const float* __restrict__ q_in, const float* __restrict__ k_in,
    const float* __restrict__ v_in,
    const float* __restrict__ Wq, const float* __restrict__ bq,
    const float* __restrict__ Wk, const float* __restrict__ bk,
    const float* __restrict__ Wv, const float* __restrict__ bv,
    float* __restrict__ Qo, float* __restrict__ Ko, float* __restrict__ Vo)
{
    const float* A; const float* W; const float* b; float* C;
    if (blockIdx.z == 0)      { A = q_in; W = Wq; b = bq; C = Qo; }
    else if (blockIdx.z == 1) { A = k_in; W = Wk; b = bk; C = Ko; }
    else                      { A = v_in; W = Wv; b = bv; C = Vo; }
    gemm_body(A, W, b, C, DMODEL, DMODEL, blockIdx.x, blockIdx.y);
}

__global__ __launch_bounds__(256) void gemm_tf32(
    const float* __restrict__ A, const float* __restrict__ W,
    const float* __restrict__ bias, float* __restrict__ C,
    int M, int N, int K)
{
    gemm_body(A, W, bias, C, N, K, blockIdx.x, blockIdx.y);
}

// ---------------------------------------------------------------------------
// TF32 flash attention v3: 128 threads, 4 warps, CTA = 64 q-rows.
// Warp owns 16 q-rows x all 64 key cols (warp-local softmax).
// Q fragments hoisted to registers; Ps overlays the Qs buffer.
// ---------------------------------------------------------------------------
#define SQ  68
#define SKS 68
#define SV  72

__global__ __launch_bounds__(128, 3) void attn_tf32(
    const float* __restrict__ Q, const float* __restrict__ K,
    const float* __restrict__ V, const int* __restrict__ mask,
    float* __restrict__ O)
{
    extern __shared__ float sm[];
    float* QPs = sm;                 // 64*68  (Qs at start, then Ps)
    float* Ks  = QPs + 64 * SQ;      // 64*68
    float* Vs  = Ks + 64 * SKS;      // 64*72
    float* ms  = Vs + 64 * SV;       // 64

    const int h   = blockIdx.x;
    const int qb  = blockIdx.y;
    const int tid = threadIdx.x;
    const int lane = tid & 31;
    const int w = tid >> 5;
    const int wbase = w * 16;
    const int gid = lane >> 2;
    const int tig = lane & 3;
    const int r0 = wbase + gid;      // owned rows: r0, r0+8

    const float LOG2E = 1.4426950408889634f;
    const float SCALE = 0.125f * LOG2E;

    // ---- Stage Q tile (64x64) to smem, cvt tf32 ----
#pragma unroll
    for (int it = 0; it < 8; it++) {
        int lin = it * 128 + tid;         // 0..1023 float4 slots
        int row = lin >> 4, c4 = (lin & 15) * 4;
        float4 v = *(const float4*)(Q + (size_t)(qb * 64 + row) * DMODEL + h * HDIM + c4);
        float4 t;
        t.x = to_tf32(v.x); t.y = to_tf32(v.y); t.z = to_tf32(v.z); t.w = to_tf32(v.w);
        *(float4*)(&QPs[row * SQ + c4]) = t;
    }
    __syncthreads();

    // ---- Hoist Q fragments to registers (8 k-steps x 4 regs) ----
    uint32_t q[8][4];
#pragma unroll
    for (int k8 = 0; k8 < 8; k8++) {
        int ks = k8 * 8;
        q[k8][0] = f2u(QPs[r0 * SQ + ks + tig]);
        q[k8][1] = f2u(QPs[(r0 + 8) * SQ + ks + tig]);
        q[k8][2] = f2u(QPs[r0 * SQ + ks + tig + 4]);
        q[k8][3] = f2u(QPs[(r0 + 8) * SQ + ks + tig + 4]);
    }
    // From here QPs is reused as Ps. Each warp only touches its own 16 rows.

    float o[8][4];
    float m0 = -1e30f, m1 = -1e30f, l0 = 0.f, l1 = 0.f;
#pragma unroll
    for (int nt = 0; nt < 8; nt++)
#pragma unroll
        for (int e = 0; e < 4; e++) o[nt][e] = 0.f;

    for (int kb = 0; kb < S_LEN / 64; kb++) {
        __syncthreads();   // everyone done with Ks/Vs from previous tile
#pragma unroll
        for (int it = 0; it < 8; it++) {
            int lin = it * 128 + tid;
            int row = lin >> 4, c4 = (lin & 15) * 4;
            size_t g = (size_t)(kb * 64 + row) * DMODEL + h * HDIM + c4;
            float4 kv = *(const float4*)(K + g);
            float4 vv = *(const float4*)(V + g);
            float4 t;
            t.x = to_tf32(kv.x); t.y = to_tf32(kv.y); t.z = to_tf32(kv.z); t.w = to_tf32(kv.w);
            *(float4*)(&Ks[row * SKS + c4]) = t;
            t.x = to_tf32(vv.x); t.y = to_tf32(vv.y); t.z = to_tf32(vv.z); t.w = to_tf32(vv.w);
            *(float4*)(&Vs[row * SV + c4]) = t;
        }
        if (tid < 64) ms[tid] = (mask[kb * 64 + tid] == 0) ? -1.0e9f * LOG2E : 0.f;
        __syncthreads();

        // ---- S = Q @ K^T : 16 rows x 64 cols per warp ----
        float s[8][4];
#pragma unroll
        for (int nt = 0; nt < 8; nt++)
#pragma unroll
            for (int e = 0; e < 4; e++) s[nt][e] = 0.f;

#pragma unroll
        for (int k8 = 0; k8 < 8; k8++) {
            int ks = k8 * 8;
#pragma unroll
            for (int nt = 0; nt < 8; nt++) {
                int kr = nt * 8 + gid;
                uint32_t b0 = f2u(Ks[kr * SKS + ks + tig]);
                uint32_t b1 = f2u(Ks[kr * SKS + ks + tig + 4]);
                mma8(s[nt], q[k8][0], q[k8][1], q[k8][2], q[k8][3], b0, b1);
            }
        }

        // ---- warp-local online softmax (log2 domain) ----
        float mx0 = -1e30f, mx1 = -1e30f;
#pragma unroll
        for (int nt = 0; nt < 8; nt++) {
            int col = nt * 8 + 2 * tig;
            float mk0 = ms[col], mk1 = ms[col + 1];
            s[nt][0] = s[nt][0] * SCALE + mk0;
            s[nt][1] = s[nt][1] * SCALE + mk1;
            s[nt][2] = s[nt][2] * SCALE + mk0;
            s[nt][3] = s[nt][3] * SCALE + mk1;
            mx0 = fmaxf(mx0, fmaxf(s[nt][0], s[nt][1]));
            mx1 = fmaxf(mx1, fmaxf(s[nt][2], s[nt][3]));
        }
        mx0 = fmaxf(mx0, __shfl_xor_sync(0xffffffffu, mx0, 1));
        mx0 = fmaxf(mx0, __shfl_xor_sync(0xffffffffu, mx0, 2));
        mx1 = fmaxf(mx1, __shfl_xor_sync(0xffffffffu, mx1, 1));
        mx1 = fmaxf(mx1, __shfl_xor_sync(0xffffffffu, mx1, 2));

        float nm0 = fmaxf(m0, mx0);
        float nm1 = fmaxf(m1, mx1);
        float f0 = exp2f(m0 - nm0);
        float f1 = exp2f(m1 - nm1);
        m0 = nm0; m1 = nm1;

        float sum0 = 0.f, sum1 = 0.f;
#pragma unroll
        for (int nt = 0; nt < 8; nt++) {
            float p0 = exp2f(s[nt][0] - nm0);
            float p1 = exp2f(s[nt][1] - nm0);
            float p2 = exp2f(s[nt][2] - nm1);
            float p3 = exp2f(s[nt][3] - nm1);
            sum0 += p0 + p1; sum1 += p2 + p3;
            int col = nt * 8 + 2 * tig;
            float2 st;
            st.x = to_tf32(p0); st.y = to_tf32(p1);
            *(float2*)(&QPs[r0 * SQ + col]) = st;
            st.x = to_tf32(p2); st.y = to_tf32(p3);
            *(float2*)(&QPs[(r0 + 8) * SQ + col]) = st;
            o[nt][0] *= f0; o[nt][1] *= f0;
            o[nt][2] *= f1; o[nt][3] *= f1;
        }
        sum0 += __shfl_xor_sync(0xffffffffu, sum0, 1);
        sum0 += __shfl_xor_sync(0xffffffffu, sum0, 2);
        sum1 += __shfl_xor_sync(0xffffffffu, sum1, 1);
        sum1 += __shfl_xor_sync(0xffffffffu, sum1, 2);
        l0 = l0 * f0 + sum0;
        l1 = l1 * f1 + sum1;
        __syncwarp();   // Ps rows warp-private: order stores before loads

        // ---- O += P @ V ----
#pragma unroll
        for (int k8 = 0; k8 < 8; k8++) {
            int ks = k8 * 8;
            uint32_t a0 = f2u(QPs[r0 * SQ + ks + tig]);
            uint32_t a1 = f2u(QPs[(r0 + 8) * SQ + ks + tig]);
            uint32_t a2 = f2u(QPs[r0 * SQ + ks + tig + 4]);
            uint32_t a3 = f2u(QPs[(r0 + 8) * SQ + ks + tig + 4]);
#pragma unroll
            for (int nt = 0; nt < 8; nt++) {
                int dc = nt * 8 + gid;
                uint32_t b0 = f2u(Vs[(ks + tig) * SV + dc]);
                uint32_t b1 = f2u(Vs[(ks + tig + 4) * SV + dc]);
                mma8(o[nt], a0, a1, a2, a3, b0, b1);
            }
        }
    }

    // ---- normalize + write ----
    float inv0 = 1.f / fmaxf(l0, 1e-20f);
    float inv1 = 1.f / fmaxf(l1, 1e-20f);
#pragma unroll
    for (int nt = 0; nt < 8; nt++) {
        int col = h * HDIM + nt * 8 + 2 * tig;
        float2 r;
        r.x = o[nt][0] * inv0; r.y = o[nt][1] * inv0;
        *(float2*)(&O[(size_t)(qb * 64 + r0) * DMODEL + col]) = r;
        r.x = o[nt][2] * inv1; r.y = o[nt][3] * inv1;
        *(float2*)(&O[(size_t)(qb * 64 + r0 + 8) * DMODEL + col]) = r;
    }
}

// ---------------------------------------------------------------------------
extern "C" void kernel_launch(void* const* d_in, const int* in_sizes, int n_in,
                              void* d_out, int out_size)
{
    (void)in_sizes; (void)n_in; (void)out_size;
    const float* query = (const float*)d_in[0];
    const float* key   = (const float*)d_in[1];
    const float* value = (const float*)d_in[2];
    const int*   amask = (const int*)  d_in[3];
    const float* Wq = (const float*)d_in[4];
    const float* bq = (const float*)d_in[5];
    const float* Wk = (const float*)d_in[6];
    const float* bk = (const float*)d_in[7];
    const float* Wv = (const float*)d_in[8];
    const float* bv = (const float*)d_in[9];
    const float* Wo = (const float*)d_in[10];
    const float* bo = (const float*)d_in[11];
    float* out = (float*)d_out;

    float *Qp, *Kp, *Vp, *Ap;
    cudaGetSymbolAddress((void**)&Qp, g_Q);
    cudaGetSymbolAddress((void**)&Kp, g_K);
    cudaGetSymbolAddress((void**)&Vp, g_V);
    cudaGetSymbolAddress((void**)&Ap, g_A);

    // Fused Q/K/V projections: one launch, 768 CTAs
    gemm_qkv<<<dim3(DMODEL / 128, S_LEN / 128, 3), 256>>>(
        query, key, value, Wq, bq, Wk, bk, Wv, bv, Qp, Kp, Vp);

    size_t smem = (size_t)(64 * SQ + 64 * SKS + 64 * SV + 64) * sizeof(float); // ~53.5 KB
    cudaFuncSetAttribute(attn_tf32,
                         cudaFuncAttributeMaxDynamicSharedMemorySize, (int)smem);
    attn_tf32<<<dim3(NHEADS, S_LEN / 64), 128, smem>>>(Qp, Kp, Vp, amask, Ap);

    gemm_tf32<<<dim3(DMODEL / 128, S_LEN / 128), 256>>>(Ap, Wo, bo, out, S_LEN, DMODEL, DMODEL);
}

// round 7
// speedup vs baseline: 6.2811x; 1.3875x over previous
#include <cuda_runtime.h>
#include <cuda_fp16.h>
#include <math.h>
#include <stdint.h>

#define S_LEN   4096
#define DMODEL  1024
#define NHEADS  16
#define HDIM    64

// Scratch (allocation-free rule: device globals)
__device__ __half g_Qh[S_LEN * DMODEL];              // [s][d] fp16
__device__ __half g_Kh[S_LEN * DMODEL];              // [s][d] fp16
__device__ __half g_VT[NHEADS * HDIM * S_LEN];       // [h][d][s] fp16
__device__ float  g_A [S_LEN * DMODEL];              // attention out fp32

// ---------------------------------------------------------------------------
// Helpers
// ---------------------------------------------------------------------------
__device__ __forceinline__ float to_tf32(float x) {
    float r;
    asm("cvt.rna.tf32.f32 %0, %1;" : "=f"(r) : "f"(x));
    return r;
}

__device__ __forceinline__ uint32_t f2u(float x) { return __float_as_uint(x); }

__device__ __forceinline__ uint32_t pack_f16(float lo, float hi) {
    __half2 h = __floats2half2_rn(lo, hi);
    return *(uint32_t*)&h;
}

__device__ __forceinline__ void mma8(float* c,
    uint32_t a0, uint32_t a1, uint32_t a2, uint32_t a3,
    uint32_t b0, uint32_t b1)
{
    asm volatile(
        "mma.sync.aligned.m16n8k8.row.col.f32.tf32.tf32.f32 "
        "{%0,%1,%2,%3}, {%4,%5,%6,%7}, {%8,%9}, {%0,%1,%2,%3};"
        : "+f"(c[0]), "+f"(c[1]), "+f"(c[2]), "+f"(c[3])
        : "r"(a0), "r"(a1), "r"(a2), "r"(a3), "r"(b0), "r"(b1));
}

__device__ __forceinline__ void mma16(float* c,
    uint32_t a0, uint32_t a1, uint32_t a2, uint32_t a3,
    uint32_t b0, uint32_t b1)
{
    asm volatile(
        "mma.sync.aligned.m16n8k16.row.col.f32.f16.f16.f32 "
        "{%0,%1,%2,%3}, {%4,%5,%6,%7}, {%8,%9}, {%0,%1,%2,%3};"
        : "+f"(c[0]), "+f"(c[1]), "+f"(c[2]), "+f"(c[3])
        : "r"(a0), "r"(a1), "r"(a2), "r"(a3), "r"(b0), "r"(b1));
}

// ---------------------------------------------------------------------------
// TF32 GEMM body. mode: 0=Q/K fp16 natural, 2=V fp16 transposed [d][s],
//                       3=fp32 natural (Wo).
// ---------------------------------------------------------------------------
#define GBK 16
#define SA  20
#define SB  136

__device__ __forceinline__ void gemm_body(
    const float* __restrict__ A, const float* __restrict__ W,
    const float* __restrict__ bias,
    float* __restrict__ Cf, __half* __restrict__ Ch,
    int N, int K, int bx, int by, int mode)
{
    __shared__ float As[128 * SA];
    __shared__ float Bs[GBK * SB];

    const int tid = threadIdx.x;
    const int lane = tid & 31;
    const int w = tid >> 5;
    const int wm = (w >> 2) * 64;
    const int wn = (w & 3) * 32;
    const int gid = lane >> 2;
    const int tig = lane & 3;

    const float* Ag = A + (size_t)by * 128 * K;
    const float* Wg = W + bx * 128;

    const int ar  = tid >> 2;
    const int ac4 = (tid & 3) * 4;
    const int br  = tid >> 5;
    const int bc4 = (tid & 31) * 4;

    float4 ra0, ra1, rb0, rb1;

    float acc[4][4][4];
#pragma unroll
    for (int mt = 0; mt < 4; mt++)
#pragma unroll
        for (int nt = 0; nt < 4; nt++)
#pragma unroll
            for (int e = 0; e < 4; e++) acc[mt][nt][e] = 0.f;

#define LOADG(k0) do { \
        ra0 = *(const float4*)(Ag + (size_t)ar * K + (k0) + ac4); \
        ra1 = *(const float4*)(Ag + (size_t)(ar + 64) * K + (k0) + ac4); \
        rb0 = *(const float4*)(Wg + (size_t)((k0) + br) * N + bc4); \
        rb1 = *(const float4*)(Wg + (size_t)((k0) + br + 8) * N + bc4); \
    } while (0)

#define STORES() do { \
        float4 t; \
        t.x = to_tf32(ra0.x); t.y = to_tf32(ra0.y); t.z = to_tf32(ra0.z); t.w = to_tf32(ra0.w); \
        *(float4*)(&As[ar * SA + ac4]) = t; \
        t.x = to_tf32(ra1.x); t.y = to_tf32(ra1.y); t.z = to_tf32(ra1.z); t.w = to_tf32(ra1.w); \
        *(float4*)(&As[(ar + 64) * SA + ac4]) = t; \
        t.x = to_tf32(rb0.x); t.y = to_tf32(rb0.y); t.z = to_tf32(rb0.z); t.w = to_tf32(rb0.w); \
        *(float4*)(&Bs[br * SB + bc4]) = t; \
        t.x = to_tf32(rb1.x); t.y = to_tf32(rb1.y); t.z = to_tf32(rb1.z); t.w = to_tf32(rb1.w); \
        *(float4*)(&Bs[(br + 8) * SB + bc4]) = t; \
    } while (0)

    const int NIT = K / GBK;
    LOADG(0);
    STORES();
    __syncthreads();

    for (int it = 0; it < NIT; it++) {
        if (it + 1 < NIT) LOADG((it + 1) * GBK);

#pragma unroll
        for (int ks = 0; ks < GBK; ks += 8) {
            uint32_t b[4][2];
#pragma unroll
            for (int nt = 0; nt < 4; nt++) {
                b[nt][0] = f2u(Bs[(ks + tig) * SB + wn + nt * 8 + gid]);
                b[nt][1] = f2u(Bs[(ks + tig + 4) * SB + wn + nt * 8 + gid]);
            }
#pragma unroll
            for (int mt = 0; mt < 4; mt++) {
                int r = wm + mt * 16 + gid;
                uint32_t a0 = f2u(As[r * SA + ks + tig]);
                uint32_t a1 = f2u(As[(r + 8) * SA + ks + tig]);
                uint32_t a2 = f2u(As[r * SA + ks + tig + 4]);
                uint32_t a3 = f2u(As[(r + 8) * SA + ks + tig + 4]);
#pragma unroll
                for (int nt = 0; nt < 4; nt++)
                    mma8(acc[mt][nt], a0, a1, a2, a3, b[nt][0], b[nt][1]);
            }
        }
        __syncthreads();
        if (it + 1 < NIT) {
            STORES();
            __syncthreads();
        }
    }

    // epilogue
#pragma unroll
    for (int nt = 0; nt < 4; nt++) {
        int col = bx * 128 + wn + nt * 8 + 2 * tig;
        float b0 = bias[col], b1 = bias[col + 1];
#pragma unroll
        for (int mt = 0; mt < 4; mt++) {
            int row = by * 128 + wm + mt * 16 + gid;
            float c0 = acc[mt][nt][0] + b0;
            float c1 = acc[mt][nt][1] + b1;
            float c2 = acc[mt][nt][2] + b0;
            float c3 = acc[mt][nt][3] + b1;
            if (mode == 3) {
                float2 o;
                o.x = c0; o.y = c1;
                *(float2*)(&Cf[(size_t)row * N + col]) = o;
                o.x = c2; o.y = c3;
                *(float2*)(&Cf[(size_t)(row + 8) * N + col]) = o;
            } else if (mode == 2) {
                // V transposed fp16: VT[col][row], row length = S_LEN
                Ch[(size_t)col * S_LEN + row]           = __float2half_rn(c0);
                Ch[(size_t)(col + 1) * S_LEN + row]     = __float2half_rn(c1);
                Ch[(size_t)col * S_LEN + row + 8]       = __float2half_rn(c2);
                Ch[(size_t)(col + 1) * S_LEN + row + 8] = __float2half_rn(c3);
            } else {
                uint32_t* Cp = (uint32_t*)Ch;
                Cp[(size_t)row * (N / 2) + (col >> 1)]       = pack_f16(c0, c1);
                Cp[(size_t)(row + 8) * (N / 2) + (col >> 1)] = pack_f16(c2, c3);
            }
        }
    }
#undef LOADG
#undef STORES
}

// Fused Q/K/V projection: blockIdx.z selects which projection.
__global__ __launch_bounds__(256) void gemm_qkv(
    const float* __restrict__ q_in, const float* __restrict__ k_in,
    const float* __restrict__ v_in,
    const float* __restrict__ Wq, const float* __restrict__ bq,
    const float* __restrict__ Wk, const float* __restrict__ bk,
    const float* __restrict__ Wv, const float* __restrict__ bv,
    __half* __restrict__ Qo, __half* __restrict__ Ko,
    __half* __restrict__ Vo)
{
    if (blockIdx.z == 0)
        gemm_body(q_in, Wq, bq, nullptr, Qo, DMODEL, DMODEL, blockIdx.x, blockIdx.y, 0);
    else if (blockIdx.z == 1)
        gemm_body(k_in, Wk, bk, nullptr, Ko, DMODEL, DMODEL, blockIdx.x, blockIdx.y, 0);
    else
        gemm_body(v_in, Wv, bv, nullptr, Vo, DMODEL, DMODEL, blockIdx.x, blockIdx.y, 2);
}

__global__ __launch_bounds__(256) void gemm_out(
    const float* __restrict__ A, const float* __restrict__ W,
    const float* __restrict__ bias, float* __restrict__ C)
{
    gemm_body(A, W, bias, C, nullptr, DMODEL, DMODEL, blockIdx.x, blockIdx.y, 3);
}

// ---------------------------------------------------------------------------
// fp16 flash attention: 256 threads, 8 warps, CTA = 128 q-rows.
// Warp owns 16 q-rows x all 64 key cols (warp-local softmax).
// All operands fp16 (m16n8k16), fp32 accumulate. V pre-transposed [h][d][s].
// Smem strides 36 u32/row -> all fragment accesses are 32-bank bijections.
// ---------------------------------------------------------------------------
#define US 36

__global__ __launch_bounds__(256, 2) void attn_f16(
    const __half* __restrict__ Qh, const __half* __restrict__ Kh,
    const __half* __restrict__ VTh, const int* __restrict__ mask,
    float* __restrict__ O)
{
    extern __shared__ uint32_t smu[];
    uint32_t* QPs = smu;                 // 128*36 u32  (Q staging, then P)
    uint32_t* Ks  = QPs + 128 * US;      // 64*36
    uint32_t* Vs  = Ks + 64 * US;        // 64*36  (V^T tile: rows=d, k-pairs)
    float*    ms  = (float*)(Vs + 64 * US);  // 64

    const int h   = blockIdx.x;
    const int qb  = blockIdx.y;
    const int tid = threadIdx.x;
    const int lane = tid & 31;
    const int w = tid >> 5;
    const int wbase = w * 16;
    const int gid = lane >> 2;
    const int tig = lane & 3;
    const int r0 = wbase + gid;          // owned rows: r0, r0+8

    const float LOG2E = 1.4426950408889634f;
    const float SCALE = 0.125f * LOG2E;

    const uint32_t* Qg = (const uint32_t*)Qh;
    const uint32_t* Kg = (const uint32_t*)Kh;
    const uint32_t* Vg = (const uint32_t*)VTh;

    // ---- Stage Q tile (128 rows x 32 u32) ----
#pragma unroll
    for (int it = 0; it < 4; it++) {
        int lin = it * 256 + tid;            // 0..1023 uint4 slots
        int row = lin >> 3, q4 = (lin & 7) * 4;
        *(uint4*)&QPs[row * US + q4] =
            *(const uint4*)(Qg + (size_t)(qb * 128 + row) * (DMODEL / 2) + h * 32 + q4);
    }
    __syncthreads();

    // ---- Hoist Q fragments (4 k16-chunks x 4 regs) ----
    uint32_t q[4][4];
#pragma unroll
    for (int c = 0; c < 4; c++) {
        q[c][0] = QPs[r0 * US + c * 8 + tig];
        q[c][1] = QPs[(r0 + 8) * US + c * 8 + tig];
        q[c][2] = QPs[r0 * US + c * 8 + tig + 4];
        q[c][3] = QPs[(r0 + 8) * US + c * 8 + tig + 4];
    }
    // QPs now reused as P staging; each warp touches only its own 16 rows.

    float o[8][4];
    float m0 = -1e30f, m1 = -1e30f, l0 = 0.f, l1 = 0.f;
#pragma unroll
    for (int nt = 0; nt < 8; nt++)
#pragma unroll
        for (int e = 0; e < 4; e++) o[nt][e] = 0.f;

    for (int kb = 0; kb < S_LEN / 64; kb++) {
        __syncthreads();   // previous tile fully consumed
#pragma unroll
        for (int it = 0; it < 2; it++) {
            int lin = it * 256 + tid;        // 0..511 uint4 slots
            int row = lin >> 3, q4 = (lin & 7) * 4;
            *(uint4*)&Ks[row * US + q4] =
                *(const uint4*)(Kg + (size_t)(kb * 64 + row) * (DMODEL / 2) + h * 32 + q4);
            *(uint4*)&Vs[row * US + q4] =
                *(const uint4*)(Vg + (size_t)(h * HDIM + row) * (S_LEN / 2) + kb * 32 + q4);
        }
        if (tid < 64) ms[tid] = (mask[kb * 64 + tid] == 0) ? -1.0e9f * LOG2E : 0.f;
        __syncthreads();

        // ---- S = Q @ K^T : 16 rows x 64 cols per warp ----
        float s[8][4];
#pragma unroll
        for (int nt = 0; nt < 8; nt++)
#pragma unroll
            for (int e = 0; e < 4; e++) s[nt][e] = 0.f;

#pragma unroll
        for (int c = 0; c < 4; c++) {
#pragma unroll
            for (int nt = 0; nt < 8; nt++) {
                int kr = nt * 8 + gid;
                uint32_t b0 = Ks[kr * US + c * 8 + tig];
                uint32_t b1 = Ks[kr * US + c * 8 + tig + 4];
                mma16(s[nt], q[c][0], q[c][1], q[c][2], q[c][3], b0, b1);
            }
        }

        // ---- warp-local online softmax (log2 domain) ----
        float mx0 = -1e30f, mx1 = -1e30f;
#pragma unroll
        for (int nt = 0; nt < 8; nt++) {
            int col = nt * 8 + 2 * tig;
            float mk0 = ms[col], mk1 = ms[col + 1];
            s[nt][0] = s[nt][0] * SCALE + mk0;
            s[nt][1] = s[nt][1] * SCALE + mk1;
            s[nt][2] = s[nt][2] * SCALE + mk0;
            s[nt][3] = s[nt][3] * SCALE + mk1;
            mx0 = fmaxf(mx0, fmaxf(s[nt][0], s[nt][1]));
            mx1 = fmaxf(mx1, fmaxf(s[nt][2], s[nt][3]));
        }
        mx0 = fmaxf(mx0, __shfl_xor_sync(0xffffffffu, mx0, 1));
        mx0 = fmaxf(mx0, __shfl_xor_sync(0xffffffffu, mx0, 2));
        mx1 = fmaxf(mx1, __shfl_xor_sync(0xffffffffu, mx1, 1));
        mx1 = fmaxf(mx1, __shfl_xor_sync(0xffffffffu, mx1, 2));

        float nm0 = fmaxf(m0, mx0);
        float nm1 = fmaxf(m1, mx1);
        float f0 = exp2f(m0 - nm0);
        float f1 = exp2f(m1 - nm1);
        m0 = nm0; m1 = nm1;

        float sum0 = 0.f, sum1 = 0.f;
#pragma unroll
        for (int nt = 0; nt < 8; nt++) {
            float p0 = exp2f(s[nt][0] - nm0);
            float p1 = exp2f(s[nt][1] - nm0);
            float p2 = exp2f(s[nt][2] - nm1);
            float p3 = exp2f(s[nt][3] - nm1);
            sum0 += p0 + p1; sum1 += p2 + p3;
            QPs[r0 * US + nt * 4 + tig]       = pack_f16(p0, p1);
            QPs[(r0 + 8) * US + nt * 4 + tig] = pack_f16(p2, p3);
            o[nt][0] *= f0; o[nt][1] *= f0;
            o[nt][2] *= f1; o[nt][3] *= f1;
        }
        sum0 += __shfl_xor_sync(0xffffffffu, sum0, 1);
        sum0 += __shfl_xor_sync(0xffffffffu, sum0, 2);
        sum1 += __shfl_xor_sync(0xffffffffu, sum1, 1);
        sum1 += __shfl_xor_sync(0xffffffffu, sum1, 2);
        l0 = l0 * f0 + sum0;
        l1 = l1 * f1 + sum1;
        __syncwarp();   // P rows warp-private: order stores before loads

        // ---- O += P @ V ----
#pragma unroll
        for (int c = 0; c < 4; c++) {
            uint32_t a0 = QPs[r0 * US + c * 8 + tig];
            uint32_t a1 = QPs[(r0 + 8) * US + c * 8 + tig];
            uint32_t a2 = QPs[r0 * US + c * 8 + tig + 4];
            uint32_t a3 = QPs[(r0 + 8) * US + c * 8 + tig + 4];
#pragma unroll
            for (int nt = 0; nt < 8; nt++) {
                int dc = nt * 8 + gid;
                uint32_t b0 = Vs[dc * US + c * 8 + tig];
                uint32_t b1 = Vs[dc * US + c * 8 + tig + 4];
                mma16(o[nt], a0, a1, a2, a3, b0, b1);
            }
        }
    }

    // ---- normalize + write fp32 ----
    float inv0 = 1.f / fmaxf(l0, 1e-20f);
    float inv1 = 1.f / fmaxf(l1, 1e-20f);
#pragma unroll
    for (int nt = 0; nt < 8; nt++) {
        int col = h * HDIM + nt * 8 + 2 * tig;
        float2 r;
        r.x = o[nt][0] * inv0; r.y = o[nt][1] * inv0;
        *(float2*)(&O[(size_t)(qb * 128 + r0) * DMODEL + col]) = r;
        r.x = o[nt][2] * inv1; r.y = o[nt][3] * inv1;
        *(float2*)(&O[(size_t)(qb * 128 + r0 + 8) * DMODEL + col]) = r;
    }
}

// ---------------------------------------------------------------------------
extern "C" void kernel_launch(void* const* d_in, const int* in_sizes, int n_in,
                              void* d_out, int out_size)
{
    (void)in_sizes; (void)n_in; (void)out_size;
    const float* query = (const float*)d_in[0];
    const float* key   = (const float*)d_in[1];
    const float* value = (const float*)d_in[2];
    const int*   amask = (const int*)  d_in[3];
    const float* Wq = (const float*)d_in[4];
    const float* bq = (const float*)d_in[5];
    const float* Wk = (const float*)d_in[6];
    const float* bk = (const float*)d_in[7];
    const float* Wv = (const float*)d_in[8];
    const float* bv = (const float*)d_in[9];
    const float* Wo = (const float*)d_in[10];
    const float* bo = (const float*)d_in[11];
    float* out = (float*)d_out;

    __half *Qhp, *Khp, *VTp;
    float *Ap;
    cudaGetSymbolAddress((void**)&Qhp, g_Qh);
    cudaGetSymbolAddress((void**)&Khp, g_Kh);
    cudaGetSymbolAddress((void**)&VTp, g_VT);
    cudaGetSymbolAddress((void**)&Ap,  g_A);

    // Fused Q/K/V projections (tf32 compute, fp16 output; V pre-transposed)
    gemm_qkv<<<dim3(DMODEL / 128, S_LEN / 128, 3), 256>>>(
        query, key, value, Wq, bq, Wk, bk, Wv, bv, Qhp, Khp, VTp);

    size_t smem = (size_t)(128 * US + 64 * US + 64 * US) * 4 + 64 * 4;  // ~36.5 KB
    attn_f16<<<dim3(NHEADS, S_LEN / 128), 256, smem>>>(Qhp, Khp, VTp, amask, Ap);

    gemm_out<<<dim3(DMODEL / 128, S_LEN / 128), 256>>>(Ap, Wo, bo, out);
}